// round 4
// baseline (speedup 1.0000x reference)
#include <cuda_runtime.h>
#include <math.h>
#include <stdint.h>

// Problem constants
#define B_    8
#define C_    320
#define N_    4096     // H*W
#define SKV_  77
#define DKV_  1024
#define HEADS_ 8
#define DH_   64
#define INNER_ 512
#define MKV_  (B_ * SKV_)   // 616

typedef unsigned long long ull;

// ---- Blackwell packed fp32x2 helpers (bit-exact fp32 per lane) ----
__device__ __forceinline__ void ffma2(ull& d, ull a, ull b) {
    asm("fma.rn.f32x2 %0, %1, %2, %0;" : "+l"(d) : "l"(a), "l"(b));
}
__device__ __forceinline__ ull pack2(float x, float y) {
    ull r; asm("mov.b64 %0, {%1, %2};" : "=l"(r) : "f"(x), "f"(y)); return r;
}
__device__ __forceinline__ float2 unpack2(ull v) {
    float2 r; asm("mov.b64 {%0, %1}, %2;" : "=f"(r.x), "=f"(r.y) : "l"(v)); return r;
}

// Scratch (allocation-free rule: __device__ globals)
__device__ float g_QpT[(size_t)B_ * INNER_ * N_];  // [b][inner][n]
__device__ float g_OT [(size_t)B_ * INNER_ * N_];  // [b][inner][n]
__device__ float g_Kp [(size_t)B_ * SKV_ * INNER_]; // pre-scaled by 1/8
__device__ float g_Vp [(size_t)B_ * SKV_ * INNER_];

// ---------------------------------------------------------------------------
// KV projection: [616,1024] @ [1024,512] -> Kp (scaled) / Vp.  z=0 -> K, z=1 -> V
// (small: 0.65 GFMA — unchanged from passing R3 version)
// ---------------------------------------------------------------------------
__global__ __launch_bounds__(256) void kv_proj_kernel(
    const float* __restrict__ kv,
    const float* __restrict__ Wk,
    const float* __restrict__ Wv)
{
    const bool isK = (blockIdx.z == 0);
    const float* __restrict__ W = isK ? Wk : Wv;
    float* __restrict__ Cout = isK ? g_Kp : g_Vp;
    const float scale = isK ? 0.125f : 1.0f;

    __shared__ float As[16][64];
    __shared__ float Bs[16][64];

    const int tid = threadIdx.x;
    const int mBase = blockIdx.x * 64;
    const int nBase = blockIdx.y * 64;
    const int rm = tid & 15;
    const int cn = tid >> 4;

    float acc[4][4] = {};

    const int aRow  = tid >> 2;
    const int aCol4 = (tid & 3) * 4;
    const int bRow  = tid >> 4;
    const int bCol4 = (tid & 15) * 4;
    const int gm = mBase + aRow;

    for (int k0 = 0; k0 < DKV_; k0 += 16) {
        float4 av = make_float4(0.f, 0.f, 0.f, 0.f);
        if (gm < MKV_)
            av = *(const float4*)(kv + (size_t)gm * DKV_ + k0 + aCol4);
        As[aCol4 + 0][aRow] = av.x;
        As[aCol4 + 1][aRow] = av.y;
        As[aCol4 + 2][aRow] = av.z;
        As[aCol4 + 3][aRow] = av.w;
        *(float4*)&Bs[bRow][bCol4] =
            *(const float4*)(W + (size_t)(k0 + bRow) * INNER_ + nBase + bCol4);
        __syncthreads();
        #pragma unroll
        for (int kk = 0; kk < 16; ++kk) {
            float a[4], bv[4];
            #pragma unroll
            for (int i = 0; i < 4; ++i) a[i]  = As[kk][rm + 16 * i];
            #pragma unroll
            for (int j = 0; j < 4; ++j) bv[j] = Bs[kk][cn + 16 * j];
            #pragma unroll
            for (int i = 0; i < 4; ++i)
                #pragma unroll
                for (int j = 0; j < 4; ++j)
                    acc[i][j] += a[i] * bv[j];
        }
        __syncthreads();
    }
    #pragma unroll
    for (int i = 0; i < 4; ++i) {
        const int m = mBase + rm + 16 * i;
        if (m < MKV_) {
            #pragma unroll
            for (int j = 0; j < 4; ++j)
                Cout[(size_t)m * INNER_ + nBase + cn + 16 * j] = acc[i][j] * scale;
        }
    }
}

// ---------------------------------------------------------------------------
// Q projection: per batch, A col-major (query is [C][N], n contiguous),
// [4096,320] @ [320,512] -> QpT[b][inner][n].
// Tile 128(M) x 128(N) x 16(K), 256 threads, 8x8 per thread via FFMA2.
// A tile stored DUPLICATED in smem so LDS.128 yields broadcast pairs.
// ---------------------------------------------------------------------------
__global__ __launch_bounds__(256) void q_proj_kernel(
    const float* __restrict__ query,
    const float* __restrict__ Wq)
{
    const int b = blockIdx.z;
    const int mBase = blockIdx.x * 128;
    const int nBase = blockIdx.y * 128;

    __shared__ float As2[16][256];   // duplicated A: pair p at floats [2p,2p+1]
    __shared__ float Bs [16][128];

    const int tid = threadIdx.x;
    const int tm = tid & 15;
    const int tn = tid >> 4;

    const float* __restrict__ A = query + (size_t)b * C_ * N_;  // A[m,k]=A[k*N_+m]

    ull acc[8][4];
    #pragma unroll
    for (int i = 0; i < 8; ++i)
        #pragma unroll
        for (int j = 0; j < 4; ++j) acc[i][j] = 0ull;

    float4 aR[2], bR[2];
    const int NT = C_ / 16;   // 20

    // prologue load (tile 0)
    #pragma unroll
    for (int r = 0; r < 2; ++r) {
        const int idx = tid + 256 * r;
        const int kc = idx >> 5, f4 = idx & 31;
        aR[r] = *(const float4*)(A  + (size_t)kc * N_    + mBase + f4 * 4);
        bR[r] = *(const float4*)(Wq + (size_t)kc * INNER_ + nBase + f4 * 4);
    }

    for (int it = 0; it < NT; ++it) {
        // store current tile to smem
        #pragma unroll
        for (int r = 0; r < 2; ++r) {
            const int idx = tid + 256 * r;
            const int kc = idx >> 5, f4 = idx & 31;
            const float4 a = aR[r];
            *(float4*)&As2[kc][f4 * 8]     = make_float4(a.x, a.x, a.y, a.y);
            *(float4*)&As2[kc][f4 * 8 + 4] = make_float4(a.z, a.z, a.w, a.w);
            *(float4*)&Bs[kc][f4 * 4] = bR[r];
        }
        __syncthreads();

        // prefetch next tile (hidden under compute)
        if (it + 1 < NT) {
            const int k0 = (it + 1) * 16;
            #pragma unroll
            for (int r = 0; r < 2; ++r) {
                const int idx = tid + 256 * r;
                const int kc = idx >> 5, f4 = idx & 31;
                aR[r] = *(const float4*)(A  + (size_t)(k0 + kc) * N_    + mBase + f4 * 4);
                bR[r] = *(const float4*)(Wq + (size_t)(k0 + kc) * INNER_ + nBase + f4 * 4);
            }
        }

        #pragma unroll
        for (int kk = 0; kk < 16; ++kk) {
            ull a[8], bb[4];
            ulonglong2 t;
            t = *(const ulonglong2*)&As2[kk][8 * tm];           a[0] = t.x; a[1] = t.y;
            t = *(const ulonglong2*)&As2[kk][8 * tm + 4];       a[2] = t.x; a[3] = t.y;
            t = *(const ulonglong2*)&As2[kk][128 + 8 * tm];     a[4] = t.x; a[5] = t.y;
            t = *(const ulonglong2*)&As2[kk][128 + 8 * tm + 4]; a[6] = t.x; a[7] = t.y;
            t = *(const ulonglong2*)&Bs[kk][4 * tn];            bb[0] = t.x; bb[1] = t.y;
            t = *(const ulonglong2*)&Bs[kk][64 + 4 * tn];       bb[2] = t.x; bb[3] = t.y;
            #pragma unroll
            for (int i = 0; i < 8; ++i)
                #pragma unroll
                for (int j = 0; j < 4; ++j)
                    ffma2(acc[i][j], a[i], bb[j]);
        }
        __syncthreads();
    }

    // epilogue: acc[i][j] -> QpT[(nBase+n)*N_ + mBase + m], float4 along m
    float* __restrict__ Cp = g_QpT + (size_t)b * INNER_ * N_;
    #pragma unroll
    for (int j = 0; j < 4; ++j) {
        const int nb = ((j >> 1) ? 64 : 0) + tn * 4 + (j & 1) * 2;
        float2 r[8];
        #pragma unroll
        for (int i = 0; i < 8; ++i) r[i] = unpack2(acc[i][j]);
        float* p0 = Cp + (size_t)(nBase + nb)     * N_ + mBase;
        float* p1 = Cp + (size_t)(nBase + nb + 1) * N_ + mBase;
        *(float4*)(p0 + tm * 4)      = make_float4(r[0].x, r[1].x, r[2].x, r[3].x);
        *(float4*)(p0 + 64 + tm * 4) = make_float4(r[4].x, r[5].x, r[6].x, r[7].x);
        *(float4*)(p1 + tm * 4)      = make_float4(r[0].y, r[1].y, r[2].y, r[3].y);
        *(float4*)(p1 + 64 + tm * 4) = make_float4(r[4].y, r[5].y, r[6].y, r[7].y);
    }
}

// ---------------------------------------------------------------------------
// Attention: one thread per query row; FFMA2 in QK^T and AV phases.
// ---------------------------------------------------------------------------
#define ATTN_SMEM_BYTES ((SKV_ * DH_ + SKV_ * 128) * (int)sizeof(float))  // 59136

__global__ __launch_bounds__(128) void attn_kernel()
{
    extern __shared__ float sm[];
    float* __restrict__ KV = sm;                 // 77*64
    float* __restrict__ L  = sm + SKV_ * DH_;    // [77][128]

    const int b = blockIdx.z;
    const int h = blockIdx.y;
    const int tid = threadIdx.x;
    const int n = blockIdx.x * 128 + tid;

    // q row -> packed pairs (coalesced gmem reads across n)
    ull q2[DH_ / 2];
    {
        const float* __restrict__ qp =
            g_QpT + (size_t)b * INNER_ * N_ + (size_t)h * DH_ * N_ + n;
        #pragma unroll
        for (int p = 0; p < DH_ / 2; ++p)
            q2[p] = pack2(qp[(size_t)(2 * p) * N_], qp[(size_t)(2 * p + 1) * N_]);
    }

    // stage K (pre-scaled)
    {
        const float* __restrict__ kp = g_Kp + (size_t)b * SKV_ * INNER_ + h * DH_;
        for (int i4 = tid; i4 < SKV_ * DH_ / 4; i4 += 128) {
            const int s = i4 >> 4, d4 = (i4 & 15) << 2;
            *(float4*)(KV + (i4 << 2)) = *(const float4*)(kp + (size_t)s * INNER_ + d4);
        }
    }
    __syncthreads();

    // logits + max
    float maxv = -1e30f;
    for (int s = 0; s < SKV_; ++s) {
        ull da = 0ull, db = 0ull;   // two chains to break RAW latency
        #pragma unroll
        for (int j = 0; j < 16; j += 2) {
            const ulonglong2 k0 = *(const ulonglong2*)(KV + s * DH_ + j * 4);
            const ulonglong2 k1 = *(const ulonglong2*)(KV + s * DH_ + j * 4 + 4);
            ffma2(da, q2[2 * j],     k0.x);
            ffma2(da, q2[2 * j + 1], k0.y);
            ffma2(db, q2[2 * j + 2], k1.x);
            ffma2(db, q2[2 * j + 3], k1.y);
        }
        const float2 pa = unpack2(da), pb = unpack2(db);
        const float dot = (pa.x + pa.y) + (pb.x + pb.y);
        L[s * 128 + tid] = dot;
        maxv = fmaxf(maxv, dot);
    }

    // softmax numerator + sum
    float sum = 0.f;
    for (int s = 0; s < SKV_; ++s) {
        const float e = __expf(L[s * 128 + tid] - maxv);
        L[s * 128 + tid] = e;
        sum += e;
    }
    const float inv = 1.f / sum;

    __syncthreads();  // all K reads done before V overwrites buffer

    // stage V
    {
        const float* __restrict__ vp = g_Vp + (size_t)b * SKV_ * INNER_ + h * DH_;
        for (int i4 = tid; i4 < SKV_ * DH_ / 4; i4 += 128) {
            const int s = i4 >> 4, d4 = (i4 & 15) << 2;
            *(float4*)(KV + (i4 << 2)) = *(const float4*)(vp + (size_t)s * INNER_ + d4);
        }
    }
    __syncthreads();

    // AV
    ull acc2[DH_ / 2];
    #pragma unroll
    for (int p = 0; p < DH_ / 2; ++p) acc2[p] = 0ull;
    for (int s = 0; s < SKV_; ++s) {
        const float p = L[s * 128 + tid];
        const ull p2 = pack2(p, p);
        #pragma unroll
        for (int j = 0; j < 16; ++j) {
            const ulonglong2 v2 = *(const ulonglong2*)(KV + s * DH_ + j * 4);
            ffma2(acc2[2 * j],     p2, v2.x);
            ffma2(acc2[2 * j + 1], p2, v2.y);
        }
    }

    // store O transposed (coalesced)
    float* __restrict__ op =
        g_OT + (size_t)b * INNER_ * N_ + (size_t)h * DH_ * N_ + n;
    #pragma unroll
    for (int p = 0; p < DH_ / 2; ++p) {
        const float2 v = unpack2(acc2[p]);
        op[(size_t)(2 * p) * N_]     = v.x * inv;
        op[(size_t)(2 * p + 1) * N_] = v.y * inv;
    }
}

// ---------------------------------------------------------------------------
// Output projection: [4096,512] @ [512,320] + bo -> out[b][c][n] (NCHW).
// Tile 128(M) x 64(N) x 16(K), 256 threads, 8x4 per thread via FFMA2.
// ---------------------------------------------------------------------------
__global__ __launch_bounds__(256) void out_proj_kernel(
    const float* __restrict__ Wo,
    const float* __restrict__ bo,
    float* __restrict__ out)
{
    const int b = blockIdx.z;
    const int mBase = blockIdx.x * 128;
    const int nBase = blockIdx.y * 64;

    __shared__ float As2[16][256];
    __shared__ float Bs [16][64];

    const int tid = threadIdx.x;
    const int tm = tid & 15;
    const int tn = tid >> 4;

    const float* __restrict__ A = g_OT + (size_t)b * INNER_ * N_;

    ull acc[8][2];
    #pragma unroll
    for (int i = 0; i < 8; ++i) { acc[i][0] = 0ull; acc[i][1] = 0ull; }

    float4 aR[2], bR;
    const int NT = INNER_ / 16;   // 32
    const int bkc = tid >> 4, bf4 = tid & 15;   // B: 256 float4 total, 1/thread

    // prologue
    #pragma unroll
    for (int r = 0; r < 2; ++r) {
        const int idx = tid + 256 * r;
        const int kc = idx >> 5, f4 = idx & 31;
        aR[r] = *(const float4*)(A + (size_t)kc * N_ + mBase + f4 * 4);
    }
    bR = *(const float4*)(Wo + (size_t)bkc * C_ + nBase + bf4 * 4);

    for (int it = 0; it < NT; ++it) {
        #pragma unroll
        for (int r = 0; r < 2; ++r) {
            const int idx = tid + 256 * r;
            const int kc = idx >> 5, f4 = idx & 31;
            const float4 a = aR[r];
            *(float4*)&As2[kc][f4 * 8]     = make_float4(a.x, a.x, a.y, a.y);
            *(float4*)&As2[kc][f4 * 8 + 4] = make_float4(a.z, a.z, a.w, a.w);
        }
        *(float4*)&Bs[bkc][bf4 * 4] = bR;
        __syncthreads();

        if (it + 1 < NT) {
            const int k0 = (it + 1) * 16;
            #pragma unroll
            for (int r = 0; r < 2; ++r) {
                const int idx = tid + 256 * r;
                const int kc = idx >> 5, f4 = idx & 31;
                aR[r] = *(const float4*)(A + (size_t)(k0 + kc) * N_ + mBase + f4 * 4);
            }
            bR = *(const float4*)(Wo + (size_t)(k0 + bkc) * C_ + nBase + bf4 * 4);
        }

        #pragma unroll
        for (int kk = 0; kk < 16; ++kk) {
            ull a[8], bb[2];
            ulonglong2 t;
            t = *(const ulonglong2*)&As2[kk][8 * tm];           a[0] = t.x; a[1] = t.y;
            t = *(const ulonglong2*)&As2[kk][8 * tm + 4];       a[2] = t.x; a[3] = t.y;
            t = *(const ulonglong2*)&As2[kk][128 + 8 * tm];     a[4] = t.x; a[5] = t.y;
            t = *(const ulonglong2*)&As2[kk][128 + 8 * tm + 4]; a[6] = t.x; a[7] = t.y;
            t = *(const ulonglong2*)&Bs[kk][4 * tn];            bb[0] = t.x; bb[1] = t.y;
            #pragma unroll
            for (int i = 0; i < 8; ++i) {
                ffma2(acc[i][0], a[i], bb[0]);
                ffma2(acc[i][1], a[i], bb[1]);
            }
        }
        __syncthreads();
    }

    // epilogue with bias, float4 stores along m (NCHW layout)
    float* __restrict__ op = out + (size_t)b * C_ * N_;
    #pragma unroll
    for (int j = 0; j < 2; ++j) {
        const int n0 = nBase + tn * 4 + j * 2;
        const float bias0 = bo[n0], bias1 = bo[n0 + 1];
        float2 r[8];
        #pragma unroll
        for (int i = 0; i < 8; ++i) r[i] = unpack2(acc[i][j]);
        float* p0 = op + (size_t)n0 * N_ + mBase;
        float* p1 = op + (size_t)(n0 + 1) * N_ + mBase;
        *(float4*)(p0 + tm * 4)      = make_float4(r[0].x + bias0, r[1].x + bias0, r[2].x + bias0, r[3].x + bias0);
        *(float4*)(p0 + 64 + tm * 4) = make_float4(r[4].x + bias0, r[5].x + bias0, r[6].x + bias0, r[7].x + bias0);
        *(float4*)(p1 + tm * 4)      = make_float4(r[0].y + bias1, r[1].y + bias1, r[2].y + bias1, r[3].y + bias1);
        *(float4*)(p1 + 64 + tm * 4) = make_float4(r[4].y + bias1, r[5].y + bias1, r[6].y + bias1, r[7].y + bias1);
    }
}

// ---------------------------------------------------------------------------
extern "C" void kernel_launch(void* const* d_in, const int* in_sizes, int n_in,
                              void* d_out, int out_size)
{
    const float* query = (const float*)d_in[0];  // [B,C,H,W]
    const float* kv    = (const float*)d_in[1];  // [B,S,DKV]
    const float* Wq    = (const float*)d_in[2];  // [C,INNER]
    const float* Wk    = (const float*)d_in[3];  // [DKV,INNER]
    const float* Wv    = (const float*)d_in[4];  // [DKV,INNER]
    const float* Wo    = (const float*)d_in[5];  // [INNER,C]
    const float* bo    = (const float*)d_in[6];  // [C]
    float* out = (float*)d_out;

    cudaFuncSetAttribute(attn_kernel,
                         cudaFuncAttributeMaxDynamicSharedMemorySize,
                         ATTN_SMEM_BYTES);

    {   // K & V projections
        dim3 grid((MKV_ + 63) / 64, INNER_ / 64, 2);   // 10 x 8 x 2
        kv_proj_kernel<<<grid, 256>>>(kv, Wk, Wv);
    }
    {   // Q projection
        dim3 grid(N_ / 128, INNER_ / 128, B_);         // 32 x 4 x 8
        q_proj_kernel<<<grid, 256>>>(query, Wq);
    }
    {   // attention
        dim3 grid(N_ / 128, HEADS_, B_);               // 32 x 8 x 8
        attn_kernel<<<grid, 128, ATTN_SMEM_BYTES>>>();
    }
    {   // output projection + bias + NCHW store
        dim3 grid(N_ / 128, C_ / 64, B_);              // 32 x 5 x 8
        out_proj_kernel<<<grid, 256>>>(Wo, bo, out);
    }
}

// round 6
// speedup vs baseline: 1.8227x; 1.8227x over previous
#include <cuda_runtime.h>
#include <math.h>
#include <stdint.h>

// Problem constants
#define B_    8
#define C_    320
#define N_    4096     // H*W  (= M of both big GEMMs)
#define SKV_  77
#define DKV_  1024
#define HEADS_ 8
#define DH_   64
#define INNER_ 512
#define MKV_  (B_ * SKV_)   // 616

typedef unsigned long long ull;

// ---- Blackwell packed fp32x2 helpers (bit-exact fp32 per lane) ----
__device__ __forceinline__ void ffma2(ull& d, ull a, ull b) {
    asm("fma.rn.f32x2 %0, %1, %2, %0;" : "+l"(d) : "l"(a), "l"(b));
}
__device__ __forceinline__ ull pack2(float x, float y) {
    ull r; asm("mov.b64 %0, {%1, %2};" : "=l"(r) : "f"(x), "f"(y)); return r;
}
__device__ __forceinline__ float2 unpack2(ull v) {
    float2 r; asm("mov.b64 {%0, %1}, %2;" : "=f"(r.x), "=f"(r.y) : "l"(v)); return r;
}

// Scratch (allocation-free rule: __device__ globals; referenced ONLY in device code)
__device__ float g_QpT[(size_t)B_ * INNER_ * N_];  // [b][inner][n]
__device__ float g_OT [(size_t)B_ * INNER_ * N_];  // [b][inner][n]
__device__ float g_Kp [(size_t)B_ * SKV_ * INNER_]; // pre-scaled by 1/8
__device__ float g_Vp [(size_t)B_ * SKV_ * INNER_];

// ---------------------------------------------------------------------------
// KV projection: [616,1024] @ [1024,512] -> Kp (scaled) / Vp.  (small GEMM)
// ---------------------------------------------------------------------------
__global__ __launch_bounds__(256) void kv_proj_kernel(
    const float* __restrict__ kv,
    const float* __restrict__ Wk,
    const float* __restrict__ Wv)
{
    const bool isK = (blockIdx.z == 0);
    const float* __restrict__ W = isK ? Wk : Wv;
    float* __restrict__ Cout = isK ? g_Kp : g_Vp;
    const float scale = isK ? 0.125f : 1.0f;

    __shared__ float As[16][64];
    __shared__ float Bs[16][64];

    const int tid = threadIdx.x;
    const int mBase = blockIdx.x * 64;
    const int nBase = blockIdx.y * 64;
    const int rm = tid & 15;
    const int cn = tid >> 4;

    float acc[4][4] = {};

    const int aRow  = tid >> 2;
    const int aCol4 = (tid & 3) * 4;
    const int bRow  = tid >> 4;
    const int bCol4 = (tid & 15) * 4;
    const int gm = mBase + aRow;

    for (int k0 = 0; k0 < DKV_; k0 += 16) {
        float4 av = make_float4(0.f, 0.f, 0.f, 0.f);
        if (gm < MKV_)
            av = *(const float4*)(kv + (size_t)gm * DKV_ + k0 + aCol4);
        As[aCol4 + 0][aRow] = av.x;
        As[aCol4 + 1][aRow] = av.y;
        As[aCol4 + 2][aRow] = av.z;
        As[aCol4 + 3][aRow] = av.w;
        *(float4*)&Bs[bRow][bCol4] =
            *(const float4*)(W + (size_t)(k0 + bRow) * INNER_ + nBase + bCol4);
        __syncthreads();
        #pragma unroll
        for (int kk = 0; kk < 16; ++kk) {
            float a[4], bv[4];
            #pragma unroll
            for (int i = 0; i < 4; ++i) a[i]  = As[kk][rm + 16 * i];
            #pragma unroll
            for (int j = 0; j < 4; ++j) bv[j] = Bs[kk][cn + 16 * j];
            #pragma unroll
            for (int i = 0; i < 4; ++i)
                #pragma unroll
                for (int j = 0; j < 4; ++j)
                    acc[i][j] += a[i] * bv[j];
        }
        __syncthreads();
    }
    #pragma unroll
    for (int i = 0; i < 4; ++i) {
        const int m = mBase + rm + 16 * i;
        if (m < MKV_) {
            #pragma unroll
            for (int j = 0; j < 4; ++j)
                Cout[(size_t)m * INNER_ + nBase + cn + 16 * j] = acc[i][j] * scale;
        }
    }
}

// ---------------------------------------------------------------------------
// Unified big GEMM, MODE-selected scratch (device globals stay device-side):
//   MODE 0 (q_proj):   A = Aarg(query, col-major [K][M]), C = g_QpT
//   MODE 1 (out_proj): A = g_OT,                          C = Carg(out) + bias
// Tile 128(M) x 64(N) x 16(K), 256 threads, 8x4 per thread.
// Conflict-free float4 smem reads:
//   A read: 8 distinct addrs @16B stride (128B span), 4-lane broadcast
//   B read: 4 distinct addrs @16B stride, 8-lane broadcast
// Inner step: 3x LDS.128 + 32 FFMA.
// ---------------------------------------------------------------------------
template <int MODE>
__global__ __launch_bounds__(256) void gemm_tn_kernel(
    const float* __restrict__ Aarg,
    const float* __restrict__ B,
    const float* __restrict__ bias,
    float* __restrict__ Carg)
{
    constexpr int K    = (MODE == 0) ? C_     : INNER_;
    constexpr int Nout = (MODE == 0) ? INNER_ : C_;

    const int b = blockIdx.z;
    const int mBase = blockIdx.x * 128;
    const int nBase = blockIdx.y * 64;

    const float* __restrict__ A =
        ((MODE == 0) ? Aarg : (const float*)g_OT) + (size_t)b * K * N_;
    float* __restrict__ Cp =
        ((MODE == 0) ? (float*)g_QpT : Carg) + (size_t)b * Nout * N_;

    __shared__ float As[16][128];
    __shared__ float Bs[16][64];

    const int tid  = threadIdx.x;
    const int warp = tid >> 5;
    const int lane = tid & 31;
    const int wm = warp & 1;
    const int wn = warp >> 1;
    const int lm = lane & 7;
    const int ln = lane >> 3;
    const int mFrag = wm * 64 + lm * 4;     // + 32 for second half
    const int nFrag = wn * 16 + ln * 4;

    float acc[8][4] = {};

    const int akc = tid >> 5;            // A staging: rows 0..7 (+8), 32 f4/row
    const int af0 = (tid & 31) * 4;
    const int bkc = tid >> 4;            // B staging: one float4 per thread
    const int bf4 = (tid & 15) * 4;

    float4 aR[2], bR;
    constexpr int NT = K / 16;

    // prologue (tile 0)
    aR[0] = *(const float4*)(A + (size_t)akc * N_ + mBase + af0);
    aR[1] = *(const float4*)(A + (size_t)(akc + 8) * N_ + mBase + af0);
    bR    = *(const float4*)(B + (size_t)bkc * Nout + nBase + bf4);

    for (int it = 0; it < NT; ++it) {
        *(float4*)&As[akc][af0]     = aR[0];
        *(float4*)&As[akc + 8][af0] = aR[1];
        *(float4*)&Bs[bkc][bf4]     = bR;
        __syncthreads();

        if (it + 1 < NT) {
            const int k0 = (it + 1) * 16;
            aR[0] = *(const float4*)(A + (size_t)(k0 + akc) * N_ + mBase + af0);
            aR[1] = *(const float4*)(A + (size_t)(k0 + akc + 8) * N_ + mBase + af0);
            bR    = *(const float4*)(B + (size_t)(k0 + bkc) * Nout + nBase + bf4);
        }

        #pragma unroll
        for (int kk = 0; kk < 16; ++kk) {
            const float4 a0 = *(const float4*)&As[kk][mFrag];
            const float4 a1 = *(const float4*)&As[kk][mFrag + 32];
            const float4 bv = *(const float4*)&Bs[kk][nFrag];
            const float a[8]  = { a0.x, a0.y, a0.z, a0.w, a1.x, a1.y, a1.z, a1.w };
            const float bb[4] = { bv.x, bv.y, bv.z, bv.w };
            #pragma unroll
            for (int i = 0; i < 8; ++i)
                #pragma unroll
                for (int j = 0; j < 4; ++j)
                    acc[i][j] += a[i] * bb[j];
        }
        __syncthreads();
    }

    // epilogue: C[n][m], float4 along m (coalesced)
    #pragma unroll
    for (int j = 0; j < 4; ++j) {
        const int n = nBase + nFrag + j;
        const float bb = (MODE == 1) ? bias[n] : 0.f;
        float* p = Cp + (size_t)n * N_ + mBase;
        *(float4*)(p + mFrag) =
            make_float4(acc[0][j] + bb, acc[1][j] + bb, acc[2][j] + bb, acc[3][j] + bb);
        *(float4*)(p + mFrag + 32) =
            make_float4(acc[4][j] + bb, acc[5][j] + bb, acc[6][j] + bb, acc[7][j] + bb);
    }
}

// ---------------------------------------------------------------------------
// Attention: one thread per query row; FFMA2 in QK^T and AV phases.
// All smem KV reads are warp-broadcast (same address) -> conflict-free.
// ---------------------------------------------------------------------------
#define ATTN_SMEM_BYTES ((SKV_ * DH_ + SKV_ * 128) * (int)sizeof(float))  // 59136

__global__ __launch_bounds__(128) void attn_kernel()
{
    extern __shared__ float sm[];
    float* __restrict__ KV = sm;                 // 77*64
    float* __restrict__ L  = sm + SKV_ * DH_;    // [77][128]

    const int b = blockIdx.z;
    const int h = blockIdx.y;
    const int tid = threadIdx.x;
    const int n = blockIdx.x * 128 + tid;

    // q row -> packed pairs (coalesced gmem reads across n)
    ull q2[DH_ / 2];
    {
        const float* __restrict__ qp =
            g_QpT + (size_t)b * INNER_ * N_ + (size_t)h * DH_ * N_ + n;
        #pragma unroll
        for (int p = 0; p < DH_ / 2; ++p)
            q2[p] = pack2(qp[(size_t)(2 * p) * N_], qp[(size_t)(2 * p + 1) * N_]);
    }

    // stage K (pre-scaled)
    {
        const float* __restrict__ kp = g_Kp + (size_t)b * SKV_ * INNER_ + h * DH_;
        for (int i4 = tid; i4 < SKV_ * DH_ / 4; i4 += 128) {
            const int s = i4 >> 4, d4 = (i4 & 15) << 2;
            *(float4*)(KV + (i4 << 2)) = *(const float4*)(kp + (size_t)s * INNER_ + d4);
        }
    }
    __syncthreads();

    // logits + max
    float maxv = -1e30f;
    for (int s = 0; s < SKV_; ++s) {
        ull da = 0ull, db = 0ull;   // two chains to break RAW latency
        #pragma unroll
        for (int j = 0; j < 16; j += 2) {
            const ulonglong2 k0 = *(const ulonglong2*)(KV + s * DH_ + j * 4);
            const ulonglong2 k1 = *(const ulonglong2*)(KV + s * DH_ + j * 4 + 4);
            ffma2(da, q2[2 * j],     k0.x);
            ffma2(da, q2[2 * j + 1], k0.y);
            ffma2(db, q2[2 * j + 2], k1.x);
            ffma2(db, q2[2 * j + 3], k1.y);
        }
        const float2 pa = unpack2(da), pb = unpack2(db);
        const float dot = (pa.x + pa.y) + (pb.x + pb.y);
        L[s * 128 + tid] = dot;
        maxv = fmaxf(maxv, dot);
    }

    // softmax numerator + sum
    float sum = 0.f;
    for (int s = 0; s < SKV_; ++s) {
        const float e = __expf(L[s * 128 + tid] - maxv);
        L[s * 128 + tid] = e;
        sum += e;
    }
    const float inv = 1.f / sum;

    __syncthreads();  // all K reads done before V overwrites buffer

    // stage V
    {
        const float* __restrict__ vp = g_Vp + (size_t)b * SKV_ * INNER_ + h * DH_;
        for (int i4 = tid; i4 < SKV_ * DH_ / 4; i4 += 128) {
            const int s = i4 >> 4, d4 = (i4 & 15) << 2;
            *(float4*)(KV + (i4 << 2)) = *(const float4*)(vp + (size_t)s * INNER_ + d4);
        }
    }
    __syncthreads();

    // AV
    ull acc2[DH_ / 2];
    #pragma unroll
    for (int p = 0; p < DH_ / 2; ++p) acc2[p] = 0ull;
    for (int s = 0; s < SKV_; ++s) {
        const float p = L[s * 128 + tid];
        const ull p2 = pack2(p, p);
        #pragma unroll
        for (int j = 0; j < 16; ++j) {
            const ulonglong2 v2 = *(const ulonglong2*)(KV + s * DH_ + j * 4);
            ffma2(acc2[2 * j],     p2, v2.x);
            ffma2(acc2[2 * j + 1], p2, v2.y);
        }
    }

    // store O transposed (coalesced)
    float* __restrict__ op =
        g_OT + (size_t)b * INNER_ * N_ + (size_t)h * DH_ * N_ + n;
    #pragma unroll
    for (int p = 0; p < DH_ / 2; ++p) {
        const float2 v = unpack2(acc2[p]);
        op[(size_t)(2 * p) * N_]     = v.x * inv;
        op[(size_t)(2 * p + 1) * N_] = v.y * inv;
    }
}

// ---------------------------------------------------------------------------
extern "C" void kernel_launch(void* const* d_in, const int* in_sizes, int n_in,
                              void* d_out, int out_size)
{
    const float* query = (const float*)d_in[0];  // [B,C,H,W]
    const float* kv    = (const float*)d_in[1];  // [B,S,DKV]
    const float* Wq    = (const float*)d_in[2];  // [C,INNER]
    const float* Wk    = (const float*)d_in[3];  // [DKV,INNER]
    const float* Wv    = (const float*)d_in[4];  // [DKV,INNER]
    const float* Wo    = (const float*)d_in[5];  // [INNER,C]
    const float* bo    = (const float*)d_in[6];  // [C]
    float* out = (float*)d_out;

    cudaFuncSetAttribute(attn_kernel,
                         cudaFuncAttributeMaxDynamicSharedMemorySize,
                         ATTN_SMEM_BYTES);

    {   // K & V projections
        dim3 grid((MKV_ + 63) / 64, INNER_ / 64, 2);   // 10 x 8 x 2
        kv_proj_kernel<<<grid, 256>>>(kv, Wk, Wv);
    }
    {   // Q projection: A=query (col-major), C -> g_QpT (selected in-kernel)
        dim3 grid(N_ / 128, INNER_ / 64, B_);          // 32 x 8 x 8
        gemm_tn_kernel<0><<<grid, 256>>>(query, Wq, nullptr, nullptr);
    }
    {   // attention
        dim3 grid(N_ / 128, HEADS_, B_);               // 32 x 8 x 8
        attn_kernel<<<grid, 128, ATTN_SMEM_BYTES>>>();
    }
    {   // output projection: A = g_OT (in-kernel), C = out (NCHW) + bias
        dim3 grid(N_ / 128, C_ / 64, B_);              // 32 x 5 x 8
        gemm_tn_kernel<1><<<grid, 256>>>(nullptr, Wo, bo, out);
    }
}

// round 7
// speedup vs baseline: 1.9743x; 1.0832x over previous
#include <cuda_runtime.h>
#include <math.h>
#include <stdint.h>

// Problem constants
#define B_    8
#define C_    320
#define N_    4096     // H*W  (= M of both big GEMMs)
#define SKV_  77
#define DKV_  1024
#define HEADS_ 8
#define DH_   64
#define INNER_ 512
#define MKV_  (B_ * SKV_)   // 616

typedef unsigned long long ull;

// ---- Blackwell packed fp32x2 helpers (bit-exact fp32 per lane) ----
__device__ __forceinline__ void ffma2(ull& d, ull a, ull b) {
    asm("fma.rn.f32x2 %0, %1, %2, %0;" : "+l"(d) : "l"(a), "l"(b));
}
__device__ __forceinline__ ull pack2(float x, float y) {
    ull r; asm("mov.b64 %0, {%1, %2};" : "=l"(r) : "f"(x), "f"(y)); return r;
}
__device__ __forceinline__ float2 unpack2(ull v) {
    float2 r; asm("mov.b64 {%0, %1}, %2;" : "=f"(r.x), "=f"(r.y) : "l"(v)); return r;
}

// Scratch (allocation-free rule: __device__ globals; referenced ONLY in device code)
__device__ float g_QpT[(size_t)B_ * INNER_ * N_];  // [b][inner][n]
__device__ float g_OT [(size_t)B_ * INNER_ * N_];  // [b][inner][n]
__device__ float g_Kp [(size_t)B_ * SKV_ * INNER_]; // pre-scaled by 1/8
__device__ float g_Vp [(size_t)B_ * SKV_ * INNER_];

// ---------------------------------------------------------------------------
// KV projection: [616,1024] @ [1024,512] -> Kp (scaled) / Vp.  (small GEMM)
// ---------------------------------------------------------------------------
__global__ __launch_bounds__(256) void kv_proj_kernel(
    const float* __restrict__ kv,
    const float* __restrict__ Wk,
    const float* __restrict__ Wv)
{
    const bool isK = (blockIdx.z == 0);
    const float* __restrict__ W = isK ? Wk : Wv;
    float* __restrict__ Cout = isK ? g_Kp : g_Vp;
    const float scale = isK ? 0.125f : 1.0f;

    __shared__ float As[16][64];
    __shared__ float Bs[16][64];

    const int tid = threadIdx.x;
    const int mBase = blockIdx.x * 64;
    const int nBase = blockIdx.y * 64;
    const int rm = tid & 15;
    const int cn = tid >> 4;

    float acc[4][4] = {};

    const int aRow  = tid >> 2;
    const int aCol4 = (tid & 3) * 4;
    const int bRow  = tid >> 4;
    const int bCol4 = (tid & 15) * 4;
    const int gm = mBase + aRow;

    for (int k0 = 0; k0 < DKV_; k0 += 16) {
        float4 av = make_float4(0.f, 0.f, 0.f, 0.f);
        if (gm < MKV_)
            av = *(const float4*)(kv + (size_t)gm * DKV_ + k0 + aCol4);
        As[aCol4 + 0][aRow] = av.x;
        As[aCol4 + 1][aRow] = av.y;
        As[aCol4 + 2][aRow] = av.z;
        As[aCol4 + 3][aRow] = av.w;
        *(float4*)&Bs[bRow][bCol4] =
            *(const float4*)(W + (size_t)(k0 + bRow) * INNER_ + nBase + bCol4);
        __syncthreads();
        #pragma unroll
        for (int kk = 0; kk < 16; ++kk) {
            float a[4], bv[4];
            #pragma unroll
            for (int i = 0; i < 4; ++i) a[i]  = As[kk][rm + 16 * i];
            #pragma unroll
            for (int j = 0; j < 4; ++j) bv[j] = Bs[kk][cn + 16 * j];
            #pragma unroll
            for (int i = 0; i < 4; ++i)
                #pragma unroll
                for (int j = 0; j < 4; ++j)
                    acc[i][j] += a[i] * bv[j];
        }
        __syncthreads();
    }
    #pragma unroll
    for (int i = 0; i < 4; ++i) {
        const int m = mBase + rm + 16 * i;
        if (m < MKV_) {
            #pragma unroll
            for (int j = 0; j < 4; ++j)
                Cout[(size_t)m * INNER_ + nBase + cn + 16 * j] = acc[i][j] * scale;
        }
    }
}

// ---------------------------------------------------------------------------
// Unified big GEMM, MODE-selected scratch (device globals stay device-side):
//   MODE 0 (q_proj):   A = Aarg(query, col-major [K][M]), C = g_QpT
//   MODE 1 (out_proj): A = g_OT,                          C = Carg(out) + bias
// Tile 128(M) x 64(N) x 16(K), 128 threads, 8x8 per thread.
// Per warp per kk: 4x LDS.128 (2048B) for 2048 lane-FMA -> 1.0 B/FMA
// (smem ceiling ~128 FMA/cyc/SM == FFMA ceiling; both saturate together).
// Conflict-free:
//   A: 8 distinct addrs @16B stride (128B span), 4-lane broadcast
//   B: 4 distinct addrs @16B stride (64B span),  8-lane broadcast
// ---------------------------------------------------------------------------
template <int MODE>
__global__ __launch_bounds__(128) void gemm_tn_kernel(
    const float* __restrict__ Aarg,
    const float* __restrict__ B,
    const float* __restrict__ bias,
    float* __restrict__ Carg)
{
    constexpr int K    = (MODE == 0) ? C_     : INNER_;
    constexpr int Nout = (MODE == 0) ? INNER_ : C_;

    const int b = blockIdx.z;
    const int mBase = blockIdx.x * 128;
    const int nBase = blockIdx.y * 64;

    const float* __restrict__ A =
        ((MODE == 0) ? Aarg : (const float*)g_OT) + (size_t)b * K * N_;
    float* __restrict__ Cp =
        ((MODE == 0) ? (float*)g_QpT : Carg) + (size_t)b * Nout * N_;

    __shared__ float As[16][128];
    __shared__ float Bs[16][64];

    const int tid  = threadIdx.x;
    const int warp = tid >> 5;
    const int lane = tid & 31;
    const int wm = warp & 1;         // m half: 0 / 64
    const int wn = warp >> 1;        // n half: 0 / 32
    const int lm = lane & 7;
    const int ln = lane >> 3;
    const int mFrag = wm * 64 + lm * 4;     // and +32
    const int nFrag = wn * 32 + ln * 4;     // and +16

    float acc[8][8] = {};

    // gmem staging (128 threads):
    //   A tile: 512 float4 -> 4/thread ;  B tile: 256 float4 -> 2/thread
    const int akc = tid >> 5;            // +4 per r ; rows 0..15 over r
    const int af4 = (tid & 31) * 4;
    const int bkc = tid >> 4;            // +8 for r=1
    const int bf4 = (tid & 15) * 4;

    float4 aR[4], bR[2];
    constexpr int NT = K / 16;

    // prologue (tile 0)
    #pragma unroll
    for (int r = 0; r < 4; ++r)
        aR[r] = *(const float4*)(A + (size_t)(akc + 4 * r) * N_ + mBase + af4);
    #pragma unroll
    for (int r = 0; r < 2; ++r)
        bR[r] = *(const float4*)(B + (size_t)(bkc + 8 * r) * Nout + nBase + bf4);

    for (int it = 0; it < NT; ++it) {
        #pragma unroll
        for (int r = 0; r < 4; ++r)
            *(float4*)&As[akc + 4 * r][af4] = aR[r];
        #pragma unroll
        for (int r = 0; r < 2; ++r)
            *(float4*)&Bs[bkc + 8 * r][bf4] = bR[r];
        __syncthreads();

        if (it + 1 < NT) {
            const int k0 = (it + 1) * 16;
            #pragma unroll
            for (int r = 0; r < 4; ++r)
                aR[r] = *(const float4*)(A + (size_t)(k0 + akc + 4 * r) * N_ + mBase + af4);
            #pragma unroll
            for (int r = 0; r < 2; ++r)
                bR[r] = *(const float4*)(B + (size_t)(k0 + bkc + 8 * r) * Nout + nBase + bf4);
        }

        #pragma unroll
        for (int kk = 0; kk < 16; ++kk) {
            const float4 a0 = *(const float4*)&As[kk][mFrag];
            const float4 a1 = *(const float4*)&As[kk][mFrag + 32];
            const float4 b0 = *(const float4*)&Bs[kk][nFrag];
            const float4 b1 = *(const float4*)&Bs[kk][nFrag + 16];
            const float a[8]  = { a0.x, a0.y, a0.z, a0.w, a1.x, a1.y, a1.z, a1.w };
            const float bb[8] = { b0.x, b0.y, b0.z, b0.w, b1.x, b1.y, b1.z, b1.w };
            #pragma unroll
            for (int i = 0; i < 8; ++i)
                #pragma unroll
                for (int j = 0; j < 8; ++j)
                    acc[i][j] += a[i] * bb[j];
        }
        __syncthreads();
    }

    // epilogue: C[n][m], float4 along m (coalesced)
    #pragma unroll
    for (int j = 0; j < 8; ++j) {
        const int n = nBase + nFrag + (j & 3) + ((j >> 2) ? 16 : 0);
        const float bb = (MODE == 1) ? bias[n] : 0.f;
        float* p = Cp + (size_t)n * N_ + mBase;
        *(float4*)(p + mFrag) =
            make_float4(acc[0][j] + bb, acc[1][j] + bb, acc[2][j] + bb, acc[3][j] + bb);
        *(float4*)(p + mFrag + 32) =
            make_float4(acc[4][j] + bb, acc[5][j] + bb, acc[6][j] + bb, acc[7][j] + bb);
    }
}

// ---------------------------------------------------------------------------
// Attention: one thread per query row; FFMA2 in QK^T and AV phases.
// All smem KV reads are warp-broadcast (same address) -> conflict-free.
// ---------------------------------------------------------------------------
#define ATTN_SMEM_BYTES ((SKV_ * DH_ + SKV_ * 128) * (int)sizeof(float))  // 59136

__global__ __launch_bounds__(128) void attn_kernel()
{
    extern __shared__ float sm[];
    float* __restrict__ KV = sm;                 // 77*64
    float* __restrict__ L  = sm + SKV_ * DH_;    // [77][128]

    const int b = blockIdx.z;
    const int h = blockIdx.y;
    const int tid = threadIdx.x;
    const int n = blockIdx.x * 128 + tid;

    // q row -> packed pairs (coalesced gmem reads across n)
    ull q2[DH_ / 2];
    {
        const float* __restrict__ qp =
            g_QpT + (size_t)b * INNER_ * N_ + (size_t)h * DH_ * N_ + n;
        #pragma unroll
        for (int p = 0; p < DH_ / 2; ++p)
            q2[p] = pack2(qp[(size_t)(2 * p) * N_], qp[(size_t)(2 * p + 1) * N_]);
    }

    // stage K (pre-scaled)
    {
        const float* __restrict__ kp = g_Kp + (size_t)b * SKV_ * INNER_ + h * DH_;
        for (int i4 = tid; i4 < SKV_ * DH_ / 4; i4 += 128) {
            const int s = i4 >> 4, d4 = (i4 & 15) << 2;
            *(float4*)(KV + (i4 << 2)) = *(const float4*)(kp + (size_t)s * INNER_ + d4);
        }
    }
    __syncthreads();

    // logits + max
    float maxv = -1e30f;
    for (int s = 0; s < SKV_; ++s) {
        ull da = 0ull, db = 0ull;   // two chains to break RAW latency
        #pragma unroll
        for (int j = 0; j < 16; j += 2) {
            const ulonglong2 k0 = *(const ulonglong2*)(KV + s * DH_ + j * 4);
            const ulonglong2 k1 = *(const ulonglong2*)(KV + s * DH_ + j * 4 + 4);
            ffma2(da, q2[2 * j],     k0.x);
            ffma2(da, q2[2 * j + 1], k0.y);
            ffma2(db, q2[2 * j + 2], k1.x);
            ffma2(db, q2[2 * j + 3], k1.y);
        }
        const float2 pa = unpack2(da), pb = unpack2(db);
        const float dot = (pa.x + pa.y) + (pb.x + pb.y);
        L[s * 128 + tid] = dot;
        maxv = fmaxf(maxv, dot);
    }

    // softmax numerator + sum
    float sum = 0.f;
    for (int s = 0; s < SKV_; ++s) {
        const float e = __expf(L[s * 128 + tid] - maxv);
        L[s * 128 + tid] = e;
        sum += e;
    }
    const float inv = 1.f / sum;

    __syncthreads();  // all K reads done before V overwrites buffer

    // stage V
    {
        const float* __restrict__ vp = g_Vp + (size_t)b * SKV_ * INNER_ + h * DH_;
        for (int i4 = tid; i4 < SKV_ * DH_ / 4; i4 += 128) {
            const int s = i4 >> 4, d4 = (i4 & 15) << 2;
            *(float4*)(KV + (i4 << 2)) = *(const float4*)(vp + (size_t)s * INNER_ + d4);
        }
    }
    __syncthreads();

    // AV
    ull acc2[DH_ / 2];
    #pragma unroll
    for (int p = 0; p < DH_ / 2; ++p) acc2[p] = 0ull;
    for (int s = 0; s < SKV_; ++s) {
        const float p = L[s * 128 + tid];
        const ull p2 = pack2(p, p);
        #pragma unroll
        for (int j = 0; j < 16; ++j) {
            const ulonglong2 v2 = *(const ulonglong2*)(KV + s * DH_ + j * 4);
            ffma2(acc2[2 * j],     p2, v2.x);
            ffma2(acc2[2 * j + 1], p2, v2.y);
        }
    }

    // store O transposed (coalesced)
    float* __restrict__ op =
        g_OT + (size_t)b * INNER_ * N_ + (size_t)h * DH_ * N_ + n;
    #pragma unroll
    for (int p = 0; p < DH_ / 2; ++p) {
        const float2 v = unpack2(acc2[p]);
        op[(size_t)(2 * p) * N_]     = v.x * inv;
        op[(size_t)(2 * p + 1) * N_] = v.y * inv;
    }
}

// ---------------------------------------------------------------------------
extern "C" void kernel_launch(void* const* d_in, const int* in_sizes, int n_in,
                              void* d_out, int out_size)
{
    const float* query = (const float*)d_in[0];  // [B,C,H,W]
    const float* kv    = (const float*)d_in[1];  // [B,S,DKV]
    const float* Wq    = (const float*)d_in[2];  // [C,INNER]
    const float* Wk    = (const float*)d_in[3];  // [DKV,INNER]
    const float* Wv    = (const float*)d_in[4];  // [DKV,INNER]
    const float* Wo    = (const float*)d_in[5];  // [INNER,C]
    const float* bo    = (const float*)d_in[6];  // [C]
    float* out = (float*)d_out;

    cudaFuncSetAttribute(attn_kernel,
                         cudaFuncAttributeMaxDynamicSharedMemorySize,
                         ATTN_SMEM_BYTES);

    {   // K & V projections
        dim3 grid((MKV_ + 63) / 64, INNER_ / 64, 2);   // 10 x 8 x 2
        kv_proj_kernel<<<grid, 256>>>(kv, Wk, Wv);
    }
    {   // Q projection: A=query (col-major), C -> g_QpT (selected in-kernel)
        dim3 grid(N_ / 128, INNER_ / 64, B_);          // 32 x 8 x 8
        gemm_tn_kernel<0><<<grid, 128>>>(query, Wq, nullptr, nullptr);
    }
    {   // attention
        dim3 grid(N_ / 128, HEADS_, B_);               // 32 x 8 x 8
        attn_kernel<<<grid, 128, ATTN_SMEM_BYTES>>>();
    }
    {   // output projection: A = g_OT (in-kernel), C = out (NCHW) + bias
        dim3 grid(N_ / 128, C_ / 64, B_);              // 32 x 5 x 8
        gemm_tn_kernel<1><<<grid, 128>>>(nullptr, Wo, bo, out);
    }
}

// round 8
// speedup vs baseline: 2.0183x; 1.0223x over previous
#include <cuda_runtime.h>
#include <math.h>
#include <stdint.h>

// Problem constants
#define B_    8
#define C_    320
#define N_    4096     // H*W  (= M of both big GEMMs)
#define SKV_  77
#define DKV_  1024
#define HEADS_ 8
#define DH_   64
#define INNER_ 512
#define MKV_  (B_ * SKV_)   // 616

typedef unsigned long long ull;

// ---- Blackwell packed fp32x2 helpers (bit-exact fp32 per lane) ----
__device__ __forceinline__ void ffma2(ull& d, ull a, ull b) {
    asm("fma.rn.f32x2 %0, %1, %2, %0;" : "+l"(d) : "l"(a), "l"(b));
}
__device__ __forceinline__ ull pack2(float x, float y) {
    ull r; asm("mov.b64 %0, {%1, %2};" : "=l"(r) : "f"(x), "f"(y)); return r;
}
__device__ __forceinline__ float2 unpack2(ull v) {
    float2 r; asm("mov.b64 {%0, %1}, %2;" : "=f"(r.x), "=f"(r.y) : "l"(v)); return r;
}

// Scratch (allocation-free rule: __device__ globals; referenced ONLY in device code)
__device__ float g_QpT[(size_t)B_ * INNER_ * N_];  // [b][inner][n]
__device__ float g_OT [(size_t)B_ * INNER_ * N_];  // [b][inner][n]
__device__ float g_Kp [(size_t)B_ * SKV_ * INNER_]; // pre-scaled by 1/8
__device__ float g_Vp [(size_t)B_ * SKV_ * INNER_];

// ---------------------------------------------------------------------------
// KV projection: [616,1024] @ [1024,512] -> Kp (scaled) / Vp.  (small GEMM)
// ---------------------------------------------------------------------------
__global__ __launch_bounds__(256) void kv_proj_kernel(
    const float* __restrict__ kv,
    const float* __restrict__ Wk,
    const float* __restrict__ Wv)
{
    const bool isK = (blockIdx.z == 0);
    const float* __restrict__ W = isK ? Wk : Wv;
    float* __restrict__ Cout = isK ? g_Kp : g_Vp;
    const float scale = isK ? 0.125f : 1.0f;

    __shared__ float As[16][64];
    __shared__ float Bs[16][64];

    const int tid = threadIdx.x;
    const int mBase = blockIdx.x * 64;
    const int nBase = blockIdx.y * 64;
    const int rm = tid & 15;
    const int cn = tid >> 4;

    float acc[4][4] = {};

    const int aRow  = tid >> 2;
    const int aCol4 = (tid & 3) * 4;
    const int bRow  = tid >> 4;
    const int bCol4 = (tid & 15) * 4;
    const int gm = mBase + aRow;

    for (int k0 = 0; k0 < DKV_; k0 += 16) {
        float4 av = make_float4(0.f, 0.f, 0.f, 0.f);
        if (gm < MKV_)
            av = *(const float4*)(kv + (size_t)gm * DKV_ + k0 + aCol4);
        As[aCol4 + 0][aRow] = av.x;
        As[aCol4 + 1][aRow] = av.y;
        As[aCol4 + 2][aRow] = av.z;
        As[aCol4 + 3][aRow] = av.w;
        *(float4*)&Bs[bRow][bCol4] =
            *(const float4*)(W + (size_t)(k0 + bRow) * INNER_ + nBase + bCol4);
        __syncthreads();
        #pragma unroll
        for (int kk = 0; kk < 16; ++kk) {
            float a[4], bv[4];
            #pragma unroll
            for (int i = 0; i < 4; ++i) a[i]  = As[kk][rm + 16 * i];
            #pragma unroll
            for (int j = 0; j < 4; ++j) bv[j] = Bs[kk][cn + 16 * j];
            #pragma unroll
            for (int i = 0; i < 4; ++i)
                #pragma unroll
                for (int j = 0; j < 4; ++j)
                    acc[i][j] += a[i] * bv[j];
        }
        __syncthreads();
    }
    #pragma unroll
    for (int i = 0; i < 4; ++i) {
        const int m = mBase + rm + 16 * i;
        if (m < MKV_) {
            #pragma unroll
            for (int j = 0; j < 4; ++j)
                Cout[(size_t)m * INNER_ + nBase + cn + 16 * j] = acc[i][j] * scale;
        }
    }
}

// ---------------------------------------------------------------------------
// Unified big GEMM, MODE-selected scratch (device globals stay device-side):
//   MODE 0 (q_proj):   A = Aarg(query, col-major [K][M]), C = g_QpT
//   MODE 1 (out_proj): A = g_OT,                          C = Carg(out) + bias
// Tile 128(M) x 64(N) x 16(K), 128 threads, 8x8 per thread.
// FFMA2 microkernel: accumulators paired over n (n,n+1).
//   B n-pairs come FREE from the ulonglong2 smem reads (consecutive floats).
//   A scalars duplicated in registers (pack2(a,a)) and reused over 4 n-pairs.
// Per kk per thread: 4 LDS.128 + 8 dup + 32 FFMA2 = 52 issue for 64 FMA
// (vs 68 scalar); smem stays 1.0 B/FMA, addresses identical to R7 ->
// conflict-free (A: 8 addrs @16B + 4-lane bcast; B: 4 addrs @16B + 8-lane bcast).
// ---------------------------------------------------------------------------
template <int MODE>
__global__ __launch_bounds__(128) void gemm_tn_kernel(
    const float* __restrict__ Aarg,
    const float* __restrict__ B,
    const float* __restrict__ bias,
    float* __restrict__ Carg)
{
    constexpr int K    = (MODE == 0) ? C_     : INNER_;
    constexpr int Nout = (MODE == 0) ? INNER_ : C_;

    const int b = blockIdx.z;
    const int mBase = blockIdx.x * 128;
    const int nBase = blockIdx.y * 64;

    const float* __restrict__ A =
        ((MODE == 0) ? Aarg : (const float*)g_OT) + (size_t)b * K * N_;
    float* __restrict__ Cp =
        ((MODE == 0) ? (float*)g_QpT : Carg) + (size_t)b * Nout * N_;

    __shared__ float As[16][128];
    __shared__ float Bs[16][64];

    const int tid  = threadIdx.x;
    const int warp = tid >> 5;
    const int lane = tid & 31;
    const int wm = warp & 1;         // m half: 0 / 64
    const int wn = warp >> 1;        // n half: 0 / 32
    const int lm = lane & 7;
    const int ln = lane >> 3;
    const int mFrag = wm * 64 + lm * 4;     // and +32
    const int nFrag = wn * 32 + ln * 4;     // and +16

    // acc[i][jp]: i = m index (8), jp = n-pair index (4):
    //   jp -> n offsets {0,1},{2,3},{16,17},{18,19} relative to nFrag
    ull acc[8][4];
    #pragma unroll
    for (int i = 0; i < 8; ++i)
        #pragma unroll
        for (int jp = 0; jp < 4; ++jp) acc[i][jp] = 0ull;

    // gmem staging (128 threads):
    //   A tile: 512 float4 -> 4/thread ;  B tile: 256 float4 -> 2/thread
    const int akc = tid >> 5;
    const int af4 = (tid & 31) * 4;
    const int bkc = tid >> 4;
    const int bf4 = (tid & 15) * 4;

    float4 aR[4], bR[2];
    constexpr int NT = K / 16;

    // prologue (tile 0)
    #pragma unroll
    for (int r = 0; r < 4; ++r)
        aR[r] = *(const float4*)(A + (size_t)(akc + 4 * r) * N_ + mBase + af4);
    #pragma unroll
    for (int r = 0; r < 2; ++r)
        bR[r] = *(const float4*)(B + (size_t)(bkc + 8 * r) * Nout + nBase + bf4);

    for (int it = 0; it < NT; ++it) {
        #pragma unroll
        for (int r = 0; r < 4; ++r)
            *(float4*)&As[akc + 4 * r][af4] = aR[r];
        #pragma unroll
        for (int r = 0; r < 2; ++r)
            *(float4*)&Bs[bkc + 8 * r][bf4] = bR[r];
        __syncthreads();

        if (it + 1 < NT) {
            const int k0 = (it + 1) * 16;
            #pragma unroll
            for (int r = 0; r < 4; ++r)
                aR[r] = *(const float4*)(A + (size_t)(k0 + akc + 4 * r) * N_ + mBase + af4);
            #pragma unroll
            for (int r = 0; r < 2; ++r)
                bR[r] = *(const float4*)(B + (size_t)(k0 + bkc + 8 * r) * Nout + nBase + bf4);
        }

        #pragma unroll
        for (int kk = 0; kk < 16; ++kk) {
            const float4 a0 = *(const float4*)&As[kk][mFrag];
            const float4 a1 = *(const float4*)&As[kk][mFrag + 32];
            const ulonglong2 b0 = *(const ulonglong2*)&Bs[kk][nFrag];
            const ulonglong2 b1 = *(const ulonglong2*)&Bs[kk][nFrag + 16];
            const ull bp[4] = { b0.x, b0.y, b1.x, b1.y };
            ull ad[8];
            ad[0] = pack2(a0.x, a0.x); ad[1] = pack2(a0.y, a0.y);
            ad[2] = pack2(a0.z, a0.z); ad[3] = pack2(a0.w, a0.w);
            ad[4] = pack2(a1.x, a1.x); ad[5] = pack2(a1.y, a1.y);
            ad[6] = pack2(a1.z, a1.z); ad[7] = pack2(a1.w, a1.w);
            #pragma unroll
            for (int i = 0; i < 8; ++i)
                #pragma unroll
                for (int jp = 0; jp < 4; ++jp)
                    ffma2(acc[i][jp], ad[i], bp[jp]);
        }
        __syncthreads();
    }

    // epilogue: C[n][m], float4 along m (coalesced)
    #pragma unroll
    for (int jp = 0; jp < 4; ++jp) {
        const int nOff = ((jp & 1) * 2) + ((jp >> 1) * 16);
        float2 v[8];
        #pragma unroll
        for (int i = 0; i < 8; ++i) v[i] = unpack2(acc[i][jp]);

        {   // lo half of pair: n = nBase + nFrag + nOff
            const int n = nBase + nFrag + nOff;
            const float bb = (MODE == 1) ? bias[n] : 0.f;
            float* p = Cp + (size_t)n * N_ + mBase;
            *(float4*)(p + mFrag) =
                make_float4(v[0].x + bb, v[1].x + bb, v[2].x + bb, v[3].x + bb);
            *(float4*)(p + mFrag + 32) =
                make_float4(v[4].x + bb, v[5].x + bb, v[6].x + bb, v[7].x + bb);
        }
        {   // hi half: n + 1
            const int n = nBase + nFrag + nOff + 1;
            const float bb = (MODE == 1) ? bias[n] : 0.f;
            float* p = Cp + (size_t)n * N_ + mBase;
            *(float4*)(p + mFrag) =
                make_float4(v[0].y + bb, v[1].y + bb, v[2].y + bb, v[3].y + bb);
            *(float4*)(p + mFrag + 32) =
                make_float4(v[4].y + bb, v[5].y + bb, v[6].y + bb, v[7].y + bb);
        }
    }
}

// ---------------------------------------------------------------------------
// Attention: one thread per query row; FFMA2 in QK^T and AV phases.
// All smem KV reads are warp-broadcast (same address) -> conflict-free.
// ---------------------------------------------------------------------------
#define ATTN_SMEM_BYTES ((SKV_ * DH_ + SKV_ * 128) * (int)sizeof(float))  // 59136

__global__ __launch_bounds__(128) void attn_kernel()
{
    extern __shared__ float sm[];
    float* __restrict__ KV = sm;                 // 77*64
    float* __restrict__ L  = sm + SKV_ * DH_;    // [77][128]

    const int b = blockIdx.z;
    const int h = blockIdx.y;
    const int tid = threadIdx.x;
    const int n = blockIdx.x * 128 + tid;

    // q row -> packed pairs (coalesced gmem reads across n)
    ull q2[DH_ / 2];
    {
        const float* __restrict__ qp =
            g_QpT + (size_t)b * INNER_ * N_ + (size_t)h * DH_ * N_ + n;
        #pragma unroll
        for (int p = 0; p < DH_ / 2; ++p)
            q2[p] = pack2(qp[(size_t)(2 * p) * N_], qp[(size_t)(2 * p + 1) * N_]);
    }

    // stage K (pre-scaled)
    {
        const float* __restrict__ kp = g_Kp + (size_t)b * SKV_ * INNER_ + h * DH_;
        for (int i4 = tid; i4 < SKV_ * DH_ / 4; i4 += 128) {
            const int s = i4 >> 4, d4 = (i4 & 15) << 2;
            *(float4*)(KV + (i4 << 2)) = *(const float4*)(kp + (size_t)s * INNER_ + d4);
        }
    }
    __syncthreads();

    // logits + max
    float maxv = -1e30f;
    for (int s = 0; s < SKV_; ++s) {
        ull da = 0ull, db = 0ull;   // two chains to break RAW latency
        #pragma unroll
        for (int j = 0; j < 16; j += 2) {
            const ulonglong2 k0 = *(const ulonglong2*)(KV + s * DH_ + j * 4);
            const ulonglong2 k1 = *(const ulonglong2*)(KV + s * DH_ + j * 4 + 4);
            ffma2(da, q2[2 * j],     k0.x);
            ffma2(da, q2[2 * j + 1], k0.y);
            ffma2(db, q2[2 * j + 2], k1.x);
            ffma2(db, q2[2 * j + 3], k1.y);
        }
        const float2 pa = unpack2(da), pb = unpack2(db);
        const float dot = (pa.x + pa.y) + (pb.x + pb.y);
        L[s * 128 + tid] = dot;
        maxv = fmaxf(maxv, dot);
    }

    // softmax numerator + sum
    float sum = 0.f;
    for (int s = 0; s < SKV_; ++s) {
        const float e = __expf(L[s * 128 + tid] - maxv);
        L[s * 128 + tid] = e;
        sum += e;
    }
    const float inv = 1.f / sum;

    __syncthreads();  // all K reads done before V overwrites buffer

    // stage V
    {
        const float* __restrict__ vp = g_Vp + (size_t)b * SKV_ * INNER_ + h * DH_;
        for (int i4 = tid; i4 < SKV_ * DH_ / 4; i4 += 128) {
            const int s = i4 >> 4, d4 = (i4 & 15) << 2;
            *(float4*)(KV + (i4 << 2)) = *(const float4*)(vp + (size_t)s * INNER_ + d4);
        }
    }
    __syncthreads();

    // AV
    ull acc2[DH_ / 2];
    #pragma unroll
    for (int p = 0; p < DH_ / 2; ++p) acc2[p] = 0ull;
    for (int s = 0; s < SKV_; ++s) {
        const float p = L[s * 128 + tid];
        const ull p2 = pack2(p, p);
        #pragma unroll
        for (int j = 0; j < 16; ++j) {
            const ulonglong2 v2 = *(const ulonglong2*)(KV + s * DH_ + j * 4);
            ffma2(acc2[2 * j],     p2, v2.x);
            ffma2(acc2[2 * j + 1], p2, v2.y);
        }
    }

    // store O transposed (coalesced)
    float* __restrict__ op =
        g_OT + (size_t)b * INNER_ * N_ + (size_t)h * DH_ * N_ + n;
    #pragma unroll
    for (int p = 0; p < DH_ / 2; ++p) {
        const float2 v = unpack2(acc2[p]);
        op[(size_t)(2 * p) * N_]     = v.x * inv;
        op[(size_t)(2 * p + 1) * N_] = v.y * inv;
    }
}

// ---------------------------------------------------------------------------
extern "C" void kernel_launch(void* const* d_in, const int* in_sizes, int n_in,
                              void* d_out, int out_size)
{
    const float* query = (const float*)d_in[0];  // [B,C,H,W]
    const float* kv    = (const float*)d_in[1];  // [B,S,DKV]
    const float* Wq    = (const float*)d_in[2];  // [C,INNER]
    const float* Wk    = (const float*)d_in[3];  // [DKV,INNER]
    const float* Wv    = (const float*)d_in[4];  // [DKV,INNER]
    const float* Wo    = (const float*)d_in[5];  // [INNER,C]
    const float* bo    = (const float*)d_in[6];  // [C]
    float* out = (float*)d_out;

    cudaFuncSetAttribute(attn_kernel,
                         cudaFuncAttributeMaxDynamicSharedMemorySize,
                         ATTN_SMEM_BYTES);

    {   // K & V projections
        dim3 grid((MKV_ + 63) / 64, INNER_ / 64, 2);   // 10 x 8 x 2
        kv_proj_kernel<<<grid, 256>>>(kv, Wk, Wv);
    }
    {   // Q projection: A=query (col-major), C -> g_QpT (selected in-kernel)
        dim3 grid(N_ / 128, INNER_ / 64, B_);          // 32 x 8 x 8
        gemm_tn_kernel<0><<<grid, 128>>>(query, Wq, nullptr, nullptr);
    }
    {   // attention
        dim3 grid(N_ / 128, HEADS_, B_);               // 32 x 8 x 8
        attn_kernel<<<grid, 128, ATTN_SMEM_BYTES>>>();
    }
    {   // output projection: A = g_OT (in-kernel), C = out (NCHW) + bias
        dim3 grid(N_ / 128, C_ / 64, B_);              // 32 x 5 x 8
        gemm_tn_kernel<1><<<grid, 128>>>(nullptr, Wo, bo, out);
    }
}